// round 11
// baseline (speedup 1.0000x reference)
#include <cuda_runtime.h>

// Problem constants
#define N_    2
#define T_    7
#define C_    96
#define HW_   9216
#define W_    96
#define PTOT  18432      // N_*HW_
#define NHEAD 4
#define HD_   24
#define K3C   288        // 3*C_

typedef unsigned long long ull;

__device__ __forceinline__ ull pack2(float x, float y) {
    ull r; asm("mov.b64 %0, {%1, %2};" : "=l"(r) : "f"(x), "f"(y)); return r;
}
__device__ __forceinline__ void unpack2(ull v, float& x, float& y) {
    asm("mov.b64 {%0, %1}, %2;" : "=f"(x), "=f"(y) : "l"(v));
}
__device__ __forceinline__ ull ffma2(ull a, ull b, ull c) {
    ull d; asm("fma.rn.f32x2 %0, %1, %2, %3;" : "=l"(d) : "l"(a), "l"(b), "l"(c)); return d;
}

// Scratch (static device arrays; no runtime allocation)
__device__ float g_kT[N_ * T_ * HW_ * C_];   // transposed index feats
__device__ float g_cat[PTOT * K3C];          // [g][k]
__device__ float g_soft[NHEAD * PTOT];       // [head][g]

// ---------------------------------------------------------------------------
// K0: transpose idxf (n,t,c,hw) -> g_kT ((n,t),hw,c).
// ---------------------------------------------------------------------------
__global__ void __launch_bounds__(256)
k0_transpose(const float* __restrict__ idxf)
{
    __shared__ float tile[4][32][33];
    int nt = blockIdx.z;
    int c0 = blockIdx.y * 32;
    int tid = threadIdx.x;
    int cL = tid >> 3, p4 = (tid & 7) * 4;
    int pL = tid >> 3, c4 = (tid & 7) * 4;

#pragma unroll
    for (int half = 0; half < 2; half++) {
        int pbase = blockIdx.x * 256 + half * 128;
#pragma unroll
        for (int b = 0; b < 4; b++) {
            int p0 = pbase + b * 32;
            float4 v = *(const float4*)(idxf + (size_t)(nt * C_ + c0 + cL) * HW_ + p0 + p4);
            tile[b][cL][p4 + 0] = v.x;
            tile[b][cL][p4 + 1] = v.y;
            tile[b][cL][p4 + 2] = v.z;
            tile[b][cL][p4 + 3] = v.w;
        }
        __syncthreads();
#pragma unroll
        for (int b = 0; b < 4; b++) {
            int p0 = pbase + b * 32;
            float4 o;
            o.x = tile[b][c4 + 0][pL];
            o.y = tile[b][c4 + 1][pL];
            o.z = tile[b][c4 + 2][pL];
            o.w = tile[b][c4 + 3][pL];
            *(float4*)(g_kT + (size_t)(nt * HW_ + p0 + pL) * C_ + c0 + c4) = o;
        }
        __syncthreads();
    }
}

// ---------------------------------------------------------------------------
// K1: unchanged (random-sector DRAM floor)
// ---------------------------------------------------------------------------
__device__ __forceinline__ void red8(float& bs, int& bi)
{
#pragma unroll
    for (int d = 4; d >= 1; d >>= 1) {
        float os = __shfl_xor_sync(0xffffffffu, bs, d, 8);
        int   oi = __shfl_xor_sync(0xffffffffu, bi, d, 8);
        if (os > bs || (os == bs && oi < bi)) { bs = os; bi = oi; }
    }
}

__global__ void __launch_bounds__(256)
k1_corr(const float* __restrict__ curr,
        const float* __restrict__ sp1,
        const float* __restrict__ sp2,
        const float* __restrict__ sp3,
        const float* __restrict__ loc)
{
    __shared__ __align__(16) float sQ[32 * 100];
    __shared__ float sLoc[2 * T_][32];

    int tx = threadIdx.x;
    int lane8 = tx & 7;
    int pb = tx >> 3;
    int g0 = blockIdx.x * 32;
    int g  = g0 + pb;
    int n = g / HW_;
    int p0blk = g0 - n * HW_;
    int t = lane8;

    {
        const float* qsrc = curr + n * C_ * HW_ + p0blk;
        for (int idx = tx; idx < C_ * 32; idx += 256) {
            int c = idx >> 5, pi = idx & 31;
            sQ[pi * 100 + c] = qsrc[c * HW_ + pi];
        }
    }
    {
        const float* lsrc = loc + (size_t)n * 2 * T_ * HW_ + p0blk;
        for (int idx = tx; idx < 2 * T_ * 32; idx += 256) {
            int pl = idx >> 5, pi = idx & 31;
            sLoc[pl][pi] = lsrc[pl * HW_ + pi];
        }
    }
    __syncthreads();

    bool val = false;
    int lin = 0;
    if (t < T_) {
        float lx = sLoc[2 * t][pb];
        float ly = sLoc[2 * t + 1][pb];
        float gx = __fadd_rn(__fdiv_rn(__fmul_rn(2.0f, lx), 95.0f), -1.0f);
        float gy = __fadd_rn(__fdiv_rn(__fmul_rn(2.0f, ly), 95.0f), -1.0f);
        float ixf = rintf(__fmul_rn(__fmul_rn(__fadd_rn(gx, 1.0f), 0.5f), 95.0f));
        float iyf = rintf(__fmul_rn(__fmul_rn(__fadd_rn(gy, 1.0f), 0.5f), 95.0f));
        val = (ixf >= 0.0f) && (ixf <= 95.0f) && (iyf >= 0.0f) && (iyf <= 95.0f);
        int ix = (int)fminf(fmaxf(ixf, 0.0f), 95.0f);
        int iy = (int)fminf(fmaxf(iyf, 0.0f), 95.0f);
        lin = iy * W_ + ix;
    }

    float sA = 0.f, sB = 0.f, sC = 0.f, sD = 0.f;
    float ksq = 0.f, qsq = 0.f;
    bool doK = (t < T_) && val;
    const float4* kp = (const float4*)(g_kT + ((size_t)(n * T_ + t) * HW_ + lin) * C_);
    const float* qrow = sQ + pb * 100;

#pragma unroll
    for (int c4 = 0; c4 < 24; c4++) {
        float4 k4 = doK ? kp[c4] : make_float4(0.f, 0.f, 0.f, 0.f);
        float4 q4 = *(const float4*)(qrow + c4 * 4);
        qsq = fmaf(q4.x, q4.x, fmaf(q4.y, q4.y, fmaf(q4.z, q4.z, fmaf(q4.w, q4.w, qsq))));
        ksq = fmaf(k4.x, k4.x, fmaf(k4.y, k4.y, fmaf(k4.z, k4.z, fmaf(k4.w, k4.w, ksq))));
        float d = fmaf(q4.x, k4.x, fmaf(q4.y, k4.y, fmaf(q4.z, k4.z, q4.w * k4.w)));
        if      (c4 <  6) sA += d;
        else if (c4 < 12) sB += d;
        else if (c4 < 18) sC += d;
        else              sD += d;
    }

    float rk = 1.0f / fmaxf(sqrtf(ksq), 1e-12f);
    float NEGINF = __int_as_float(0xff800000);
    float b0 = (t < T_) ? sA * rk : NEGINF;
    float b1 = (t < T_) ? sB * rk : NEGINF;
    float b2 = (t < T_) ? sC * rk : NEGINF;
    float b3 = (t < T_) ? sD * rk : NEGINF;
    int i0 = t, i1 = t, i2 = t, i3 = t;
    red8(b0, i0);
    red8(b1, i1);
    red8(b2, i2);
    red8(b3, i3);

    float rq = 1.0f / fmaxf(sqrtf(qsq), 1e-12f);
    if (lane8 == 0) g_soft[0 * PTOT + g] = b0 * rq;
    if (lane8 == 1) g_soft[1 * PTOT + g] = b1 * rq;
    if (lane8 == 2) g_soft[2 * PTOT + g] = b2 * rq;
    if (lane8 == 3) g_soft[3 * PTOT + g] = b3 * rq;

    int vflag = val ? 1 : 0;
    int bw[NHEAD], lw[NHEAD], vw[NHEAD];
    bw[0] = i0; bw[1] = i1; bw[2] = i2; bw[3] = i3;
#pragma unroll
    for (int h = 0; h < NHEAD; h++) {
        lw[h] = __shfl_sync(0xffffffffu, lin,   bw[h], 8);
        vw[h] = __shfl_sync(0xffffffffu, vflag, bw[h], 8);
    }

    float* catg = g_cat + (size_t)g * K3C;
#pragma unroll
    for (int h = 0; h < NHEAD; h++) {
        int bofs = ((n * T_ + bw[h]) * C_ + h * HD_) * HW_ + lw[h];
        bool v = (vw[h] != 0);
#pragma unroll
        for (int set = 0; set < 3; set++) {
            const float* sp = (set == 0) ? sp1 : ((set == 1) ? sp2 : sp3);
#pragma unroll
            for (int j2 = 0; j2 < 3; j2++) {
                int cc = lane8 + j2 * 8;
                float vv = v ? __ldg(sp + bofs + cc * HW_) : 0.0f;
                catg[set * C_ + h * HD_ + cc] = vv;
            }
        }
    }
}

// ---------------------------------------------------------------------------
// K23 fused: KB=32, static smem, 192 threads, 8x4 microtile (LDS.128 A-side).
// ---------------------------------------------------------------------------
#define PB 64
#define KB 32
#define AP 104   // As pitch: 16B-aligned rows, 4-way STS conflict (vs 8-way @100)
#define BP 68
#define NT 192

__global__ void __launch_bounds__(NT, 2)
k23_gemm(const float* __restrict__ Fw, const float* __restrict__ fb,
         const float* __restrict__ Pw, const float* __restrict__ pbias,
         const float* __restrict__ anchor, float* __restrict__ out)
{
    __shared__ __align__(16) float As[KB * AP];   // 3328 floats
    __shared__ __align__(16) float Bs[KB * BP];   // 2176
    __shared__ __align__(16) float Us[C_ * BP];   // 6528  (total 48128 B)

    int g0 = blockIdx.x * PB;
    int n  = g0 / HW_;
    int p0 = g0 - n * HW_;
    int tx = threadIdx.x;
    int m0   = (tx >> 4) * 8;      // 12 groups of 8 rows (heads = 3 groups each)
    int col0 = (tx & 15) * 4;

    ull acc[4][4];
#pragma unroll
    for (int jp = 0; jp < 4; jp++)
#pragma unroll
        for (int c = 0; c < 4; c++) acc[jp][c] = 0ull;

    const float4* cat4 = (const float4*)g_cat;

    float  aR[16];    // 96*32/192
    float4 bR[3];     // 512/192 (guarded)

#pragma unroll
    for (int r = 0; r < 16; r++) {
        int i = r * NT + tx;
        aR[r] = Fw[(i >> 5) * K3C + (i & 31)];
    }
#pragma unroll
    for (int r = 0; r < 3; r++) {
        int i = r * NT + tx;
        if (i < 512) bR[r] = cat4[(size_t)(g0 + (i >> 3)) * (K3C / 4) + (i & 7)];
    }

    // ---- phase 1: U = Fw @ cat  (9 chunks of 32) ----
    for (int kb = 0; kb < K3C; kb += KB) {
#pragma unroll
        for (int r = 0; r < 16; r++) {
            int i = r * NT + tx;
            As[(i & 31) * AP + (i >> 5)] = aR[r];
        }
#pragma unroll
        for (int r = 0; r < 3; r++) {
            int i = r * NT + tx;
            if (i < 512) {
                int col = i >> 3, kk = (i & 7) * 4;
                Bs[(kk + 0) * BP + col] = bR[r].x;
                Bs[(kk + 1) * BP + col] = bR[r].y;
                Bs[(kk + 2) * BP + col] = bR[r].z;
                Bs[(kk + 3) * BP + col] = bR[r].w;
            }
        }
        __syncthreads();

        int kn = kb + KB;
        if (kn < K3C) {
#pragma unroll
            for (int r = 0; r < 16; r++) {
                int i = r * NT + tx;
                aR[r] = Fw[(i >> 5) * K3C + kn + (i & 31)];
            }
#pragma unroll
            for (int r = 0; r < 3; r++) {
                int i = r * NT + tx;
                if (i < 512) bR[r] = cat4[(size_t)(g0 + (i >> 3)) * (K3C / 4) + (kn >> 2) + (i & 7)];
            }
        } else {
            // prefetch Pw chunk 0 for phase 2
#pragma unroll
            for (int r = 0; r < 16; r++) {
                int i = r * NT + tx;
                aR[r] = Pw[(i >> 5) * C_ + (i & 31)];
            }
        }

#pragma unroll
        for (int kk = 0; kk < KB; kk++) {
            ulonglong2 aa = *(const ulonglong2*)&As[kk * AP + m0];      // rows m0..m0+3
            ulonglong2 ab = *(const ulonglong2*)&As[kk * AP + m0 + 4];  // rows m0+4..m0+7
            float4 b = *(const float4*)&Bs[kk * BP + col0];
            ull bx = pack2(b.x, b.x), by = pack2(b.y, b.y);
            ull bz = pack2(b.z, b.z), bw = pack2(b.w, b.w);
            acc[0][0] = ffma2(aa.x, bx, acc[0][0]);
            acc[0][1] = ffma2(aa.x, by, acc[0][1]);
            acc[0][2] = ffma2(aa.x, bz, acc[0][2]);
            acc[0][3] = ffma2(aa.x, bw, acc[0][3]);
            acc[1][0] = ffma2(aa.y, bx, acc[1][0]);
            acc[1][1] = ffma2(aa.y, by, acc[1][1]);
            acc[1][2] = ffma2(aa.y, bz, acc[1][2]);
            acc[1][3] = ffma2(aa.y, bw, acc[1][3]);
            acc[2][0] = ffma2(ab.x, bx, acc[2][0]);
            acc[2][1] = ffma2(ab.x, by, acc[2][1]);
            acc[2][2] = ffma2(ab.x, bz, acc[2][2]);
            acc[2][3] = ffma2(ab.x, bw, acc[2][3]);
            acc[3][0] = ffma2(ab.y, bx, acc[3][0]);
            acc[3][1] = ffma2(ab.y, by, acc[3][1]);
            acc[3][2] = ffma2(ab.y, bz, acc[3][2]);
            acc[3][3] = ffma2(ab.y, bw, acc[3][3]);
        }
        __syncthreads();
    }

    // epilogue 1: +fb, *soft -> Us   (8-row group lies within one head)
    {
        int head = m0 / HD_;
        float4 sf = *(const float4*)&g_soft[head * PTOT + g0 + col0];
#pragma unroll
        for (int jp = 0; jp < 4; jp++) {
            int m = m0 + 2 * jp;
            float f0 = fb[m], f1 = fb[m + 1];
            float4 r0, r1;
            unpack2(acc[jp][0], r0.x, r1.x);
            unpack2(acc[jp][1], r0.y, r1.y);
            unpack2(acc[jp][2], r0.z, r1.z);
            unpack2(acc[jp][3], r0.w, r1.w);
            r0.x = (r0.x + f0) * sf.x; r0.y = (r0.y + f0) * sf.y;
            r0.z = (r0.z + f0) * sf.z; r0.w = (r0.w + f0) * sf.w;
            r1.x = (r1.x + f1) * sf.x; r1.y = (r1.y + f1) * sf.y;
            r1.z = (r1.z + f1) * sf.z; r1.w = (r1.w + f1) * sf.w;
            *(float4*)&Us[m * BP + col0] = r0;
            *(float4*)&Us[(m + 1) * BP + col0] = r1;
        }
    }
    __syncthreads();

    // ---- phase 2: out = Pw @ U  (3 chunks of 32) ----
    ull acc2[4][4];
#pragma unroll
    for (int jp = 0; jp < 4; jp++)
#pragma unroll
        for (int c = 0; c < 4; c++) acc2[jp][c] = 0ull;

    for (int cb = 0; cb < C_; cb += KB) {
#pragma unroll
        for (int r = 0; r < 16; r++) {
            int i = r * NT + tx;
            As[(i & 31) * AP + (i >> 5)] = aR[r];
        }
        __syncthreads();

        int cn = cb + KB;
        if (cn < C_) {
#pragma unroll
            for (int r = 0; r < 16; r++) {
                int i = r * NT + tx;
                aR[r] = Pw[(i >> 5) * C_ + cn + (i & 31)];
            }
        }

#pragma unroll
        for (int kk = 0; kk < KB; kk++) {
            ulonglong2 aa = *(const ulonglong2*)&As[kk * AP + m0];
            ulonglong2 ab = *(const ulonglong2*)&As[kk * AP + m0 + 4];
            float4 b = *(const float4*)&Us[(cb + kk) * BP + col0];
            ull bx = pack2(b.x, b.x), by = pack2(b.y, b.y);
            ull bz = pack2(b.z, b.z), bw = pack2(b.w, b.w);
            acc2[0][0] = ffma2(aa.x, bx, acc2[0][0]);
            acc2[0][1] = ffma2(aa.x, by, acc2[0][1]);
            acc2[0][2] = ffma2(aa.x, bz, acc2[0][2]);
            acc2[0][3] = ffma2(aa.x, bw, acc2[0][3]);
            acc2[1][0] = ffma2(aa.y, bx, acc2[1][0]);
            acc2[1][1] = ffma2(aa.y, by, acc2[1][1]);
            acc2[1][2] = ffma2(aa.y, bz, acc2[1][2]);
            acc2[1][3] = ffma2(aa.y, bw, acc2[1][3]);
            acc2[2][0] = ffma2(ab.x, bx, acc2[2][0]);
            acc2[2][1] = ffma2(ab.x, by, acc2[2][1]);
            acc2[2][2] = ffma2(ab.x, bz, acc2[2][2]);
            acc2[2][3] = ffma2(ab.x, bw, acc2[2][3]);
            acc2[3][0] = ffma2(ab.y, bx, acc2[3][0]);
            acc2[3][1] = ffma2(ab.y, by, acc2[3][1]);
            acc2[3][2] = ffma2(ab.y, bz, acc2[3][2]);
            acc2[3][3] = ffma2(ab.y, bw, acc2[3][3]);
        }
        __syncthreads();
    }

    // epilogue 2: + pbias + anchor -> out
#pragma unroll
    for (int jp = 0; jp < 4; jp++) {
        int d = m0 + 2 * jp;
        float p0b = pbias[d], p1b = pbias[d + 1];
        float4 a0 = *(const float4*)(anchor + (size_t)(n * C_ + d) * HW_ + p0 + col0);
        float4 a1 = *(const float4*)(anchor + (size_t)(n * C_ + d + 1) * HW_ + p0 + col0);
        float4 r0, r1;
        unpack2(acc2[jp][0], r0.x, r1.x);
        unpack2(acc2[jp][1], r0.y, r1.y);
        unpack2(acc2[jp][2], r0.z, r1.z);
        unpack2(acc2[jp][3], r0.w, r1.w);
        r0.x = r0.x + p0b + a0.x; r0.y = r0.y + p0b + a0.y;
        r0.z = r0.z + p0b + a0.z; r0.w = r0.w + p0b + a0.w;
        r1.x = r1.x + p1b + a1.x; r1.y = r1.y + p1b + a1.y;
        r1.z = r1.z + p1b + a1.z; r1.w = r1.w + p1b + a1.w;
        *(float4*)(out + (size_t)(n * C_ + d) * HW_ + p0 + col0) = r0;
        *(float4*)(out + (size_t)(n * C_ + d + 1) * HW_ + p0 + col0) = r1;
    }
}

// ---------------------------------------------------------------------------
extern "C" void kernel_launch(void* const* d_in, const int* in_sizes, int n_in,
                              void* d_out, int out_size)
{
    const float* curr   = (const float*)d_in[0];
    const float* idxf   = (const float*)d_in[1];
    const float* anchor = (const float*)d_in[2];
    const float* s1     = (const float*)d_in[3];
    const float* s2     = (const float*)d_in[4];
    const float* s3     = (const float*)d_in[5];
    const float* loc    = (const float*)d_in[6];
    const float* pw     = (const float*)d_in[7];
    const float* pbv    = (const float*)d_in[8];
    const float* fw     = (const float*)d_in[9];
    const float* fbv    = (const float*)d_in[10];
    float* out = (float*)d_out;

    k0_transpose<<<dim3(HW_ / 256, C_ / 32, N_ * T_), 256>>>(idxf);
    k1_corr<<<PTOT / 32, 256>>>(curr, s1, s2, s3, loc);
    k23_gemm<<<PTOT / PB, NT>>>(fw, fbv, pw, pbv, anchor, out);
}

// round 14
// speedup vs baseline: 1.0755x; 1.0755x over previous
#include <cuda_runtime.h>
#include <cuda_bf16.h>

// Problem constants
#define N_    2
#define T_    7
#define C_    96
#define HW_   9216
#define W_    96
#define PTOT  18432      // N_*HW_
#define NHEAD 4
#define HD_   24
#define K3C   288        // 3*C_
#define KU    144        // K3C/2 u32 words per pixel row

typedef unsigned int       u32;
typedef unsigned long long ull;

__device__ __forceinline__ ull pack2(float x, float y) {
    ull r; asm("mov.b64 %0, {%1, %2};" : "=l"(r) : "f"(x), "f"(y)); return r;
}
__device__ __forceinline__ void unpack2(ull v, float& x, float& y) {
    asm("mov.b64 {%0, %1}, %2;" : "=f"(x), "=f"(y) : "l"(v));
}
__device__ __forceinline__ ull ffma2(ull a, ull b, ull c) {
    ull d; asm("fma.rn.f32x2 %0, %1, %2, %3;" : "=l"(d) : "l"(a), "l"(b), "l"(c)); return d;
}
__device__ __forceinline__ u32 bf16x2_pack(float lo, float hi) {
    u32 r;
    asm("cvt.rn.bf16x2.f32 %0, %1, %2;" : "=r"(r) : "f"(hi), "f"(lo));  // first src = upper half
    return r;
}
// bf16 -> f32 is a 16-bit left shift of the bit pattern
__device__ __forceinline__ float bf_lo(u32 w) { return __uint_as_float(w << 16); }
__device__ __forceinline__ float bf_hi(u32 w) { return __uint_as_float(w & 0xFFFF0000u); }

// Scratch (static device arrays; no runtime allocation)
__device__ float g_kT[N_ * T_ * HW_ * C_];   // transposed index feats
__device__ u32   g_cat[PTOT * KU];           // [g][144] bf16x2 pairs
__device__ float g_soft[NHEAD * PTOT];       // [head][g]

// ---------------------------------------------------------------------------
// K0: transpose idxf (n,t,c,hw) -> g_kT ((n,t),hw,c).   [R7, unchanged]
// ---------------------------------------------------------------------------
__global__ void __launch_bounds__(256)
k0_transpose(const float* __restrict__ idxf)
{
    __shared__ float tile[4][32][33];
    int nt = blockIdx.z;
    int c0 = blockIdx.y * 32;
    int tid = threadIdx.x;
    int cL = tid >> 3, p4 = (tid & 7) * 4;
    int pL = tid >> 3, c4 = (tid & 7) * 4;

#pragma unroll
    for (int half = 0; half < 2; half++) {
        int pbase = blockIdx.x * 256 + half * 128;
#pragma unroll
        for (int b = 0; b < 4; b++) {
            int p0 = pbase + b * 32;
            float4 v = *(const float4*)(idxf + (size_t)(nt * C_ + c0 + cL) * HW_ + p0 + p4);
            tile[b][cL][p4 + 0] = v.x;
            tile[b][cL][p4 + 1] = v.y;
            tile[b][cL][p4 + 2] = v.z;
            tile[b][cL][p4 + 3] = v.w;
        }
        __syncthreads();
#pragma unroll
        for (int b = 0; b < 4; b++) {
            int p0 = pbase + b * 32;
            float4 o;
            o.x = tile[b][c4 + 0][pL];
            o.y = tile[b][c4 + 1][pL];
            o.z = tile[b][c4 + 2][pL];
            o.w = tile[b][c4 + 3][pL];
            *(float4*)(g_kT + (size_t)(nt * HW_ + p0 + pL) * C_ + c0 + c4) = o;
        }
        __syncthreads();
    }
}

// ---------------------------------------------------------------------------
// K1: correlation + argmax + winner gather; cat stored as bf16x2 pairs.
// ---------------------------------------------------------------------------
__device__ __forceinline__ void red8(float& bs, int& bi)
{
#pragma unroll
    for (int d = 4; d >= 1; d >>= 1) {
        float os = __shfl_xor_sync(0xffffffffu, bs, d, 8);
        int   oi = __shfl_xor_sync(0xffffffffu, bi, d, 8);
        if (os > bs || (os == bs && oi < bi)) { bs = os; bi = oi; }
    }
}

__global__ void __launch_bounds__(256)
k1_corr(const float* __restrict__ curr,
        const float* __restrict__ sp1,
        const float* __restrict__ sp2,
        const float* __restrict__ sp3,
        const float* __restrict__ loc)
{
    __shared__ __align__(16) float sQ[32 * 100];
    __shared__ float sLoc[2 * T_][32];

    int tx = threadIdx.x;
    int lane8 = tx & 7;
    int pb = tx >> 3;
    int g0 = blockIdx.x * 32;
    int g  = g0 + pb;
    int n = g / HW_;
    int p0blk = g0 - n * HW_;
    int t = lane8;

    {
        const float* qsrc = curr + n * C_ * HW_ + p0blk;
        for (int idx = tx; idx < C_ * 32; idx += 256) {
            int c = idx >> 5, pi = idx & 31;
            sQ[pi * 100 + c] = qsrc[c * HW_ + pi];
        }
    }
    {
        const float* lsrc = loc + (size_t)n * 2 * T_ * HW_ + p0blk;
        for (int idx = tx; idx < 2 * T_ * 32; idx += 256) {
            int pl = idx >> 5, pi = idx & 31;
            sLoc[pl][pi] = lsrc[pl * HW_ + pi];
        }
    }
    __syncthreads();

    bool val = false;
    int lin = 0;
    if (t < T_) {
        float lx = sLoc[2 * t][pb];
        float ly = sLoc[2 * t + 1][pb];
        float gx = __fadd_rn(__fdiv_rn(__fmul_rn(2.0f, lx), 95.0f), -1.0f);
        float gy = __fadd_rn(__fdiv_rn(__fmul_rn(2.0f, ly), 95.0f), -1.0f);
        float ixf = rintf(__fmul_rn(__fmul_rn(__fadd_rn(gx, 1.0f), 0.5f), 95.0f));
        float iyf = rintf(__fmul_rn(__fmul_rn(__fadd_rn(gy, 1.0f), 0.5f), 95.0f));
        val = (ixf >= 0.0f) && (ixf <= 95.0f) && (iyf >= 0.0f) && (iyf <= 95.0f);
        int ix = (int)fminf(fmaxf(ixf, 0.0f), 95.0f);
        int iy = (int)fminf(fmaxf(iyf, 0.0f), 95.0f);
        lin = iy * W_ + ix;
    }

    float sA = 0.f, sB = 0.f, sC = 0.f, sD = 0.f;
    float ksq = 0.f, qsq = 0.f;
    bool doK = (t < T_) && val;
    const float4* kp = (const float4*)(g_kT + ((size_t)(n * T_ + t) * HW_ + lin) * C_);
    const float* qrow = sQ + pb * 100;

#pragma unroll
    for (int c4 = 0; c4 < 24; c4++) {
        float4 k4 = doK ? kp[c4] : make_float4(0.f, 0.f, 0.f, 0.f);
        float4 q4 = *(const float4*)(qrow + c4 * 4);
        qsq = fmaf(q4.x, q4.x, fmaf(q4.y, q4.y, fmaf(q4.z, q4.z, fmaf(q4.w, q4.w, qsq))));
        ksq = fmaf(k4.x, k4.x, fmaf(k4.y, k4.y, fmaf(k4.z, k4.z, fmaf(k4.w, k4.w, ksq))));
        float d = fmaf(q4.x, k4.x, fmaf(q4.y, k4.y, fmaf(q4.z, k4.z, q4.w * k4.w)));
        if      (c4 <  6) sA += d;
        else if (c4 < 12) sB += d;
        else if (c4 < 18) sC += d;
        else              sD += d;
    }

    float rk = 1.0f / fmaxf(sqrtf(ksq), 1e-12f);
    float NEGINF = __int_as_float(0xff800000);
    float b0 = (t < T_) ? sA * rk : NEGINF;
    float b1 = (t < T_) ? sB * rk : NEGINF;
    float b2 = (t < T_) ? sC * rk : NEGINF;
    float b3 = (t < T_) ? sD * rk : NEGINF;
    int i0 = t, i1 = t, i2 = t, i3 = t;
    red8(b0, i0);
    red8(b1, i1);
    red8(b2, i2);
    red8(b3, i3);

    float rq = 1.0f / fmaxf(sqrtf(qsq), 1e-12f);
    if (lane8 == 0) g_soft[0 * PTOT + g] = b0 * rq;
    if (lane8 == 1) g_soft[1 * PTOT + g] = b1 * rq;
    if (lane8 == 2) g_soft[2 * PTOT + g] = b2 * rq;
    if (lane8 == 3) g_soft[3 * PTOT + g] = b3 * rq;

    int vflag = val ? 1 : 0;
    int bw[NHEAD], lw[NHEAD], vw[NHEAD];
    bw[0] = i0; bw[1] = i1; bw[2] = i2; bw[3] = i3;
#pragma unroll
    for (int h = 0; h < NHEAD; h++) {
        lw[h] = __shfl_sync(0xffffffffu, lin,   bw[h], 8);
        vw[h] = __shfl_sync(0xffffffffu, vflag, bw[h], 8);
    }

    u32* catg = g_cat + (size_t)g * KU;
#pragma unroll
    for (int h = 0; h < NHEAD; h++) {
        int bofs = ((n * T_ + bw[h]) * C_ + h * HD_) * HW_ + lw[h];
        bool v = (vw[h] != 0);
        // 36 bf16x2 pairs per head (3 sets x 12); pair pi covers channels 2pi,2pi+1
#pragma unroll
        for (int j = 0; j < 5; j++) {
            int pi = lane8 + j * 8;
            if (j < 4 || pi < 36) {
                int ch0 = 2 * pi;              // 0..70, even
                int set = ch0 / 24;
                int cc  = ch0 - set * 24;
                const float* sp = (set == 0) ? sp1 : ((set == 1) ? sp2 : sp3);
                float v0 = v ? __ldg(sp + bofs + cc * HW_)       : 0.0f;
                float v1 = v ? __ldg(sp + bofs + (cc + 1) * HW_) : 0.0f;
                catg[set * 48 + h * 12 + (cc >> 1)] = bf16x2_pack(v0, v1);
            }
        }
    }
}

// ---------------------------------------------------------------------------
// K23 fused [R7 shape]: KB=32, 256 threads, 6x4 FFMA2 microtile, AP=104.
// ---------------------------------------------------------------------------
#define PB 64
#define KB 32
#define AP 104   // 4-way STS bank conflict (vs 8-way at 100); rows 8B-aligned
#define BP 68

__global__ void __launch_bounds__(256, 2)
k23_gemm(const float* __restrict__ Fw, const float* __restrict__ fb,
         const float* __restrict__ Pw, const float* __restrict__ pbias,
         const float* __restrict__ anchor, float* __restrict__ out)
{
    __shared__ __align__(16) float As[KB * AP];
    __shared__ __align__(16) float Bs[KB * BP];
    __shared__ __align__(16) float Us[C_ * BP];

    int g0 = blockIdx.x * PB;
    int n  = g0 / HW_;
    int p0 = g0 - n * HW_;
    int tx = threadIdx.x;
    int m0   = (tx >> 4) * 6;
    int col0 = (tx & 15) * 4;

    ull acc[3][4];
#pragma unroll
    for (int jp = 0; jp < 3; jp++)
#pragma unroll
        for (int c = 0; c < 4; c++) acc[jp][c] = 0ull;

    const uint4* catu4 = (const uint4*)g_cat;   // rows: 36 uint4 per pixel

    float aR[12];
    uint4 bR;          // 8 bf16 values = 8 k-slots for one column

    int bcol = tx >> 2;          // 0..63
    int bq   = tx & 3;           // which uint4 within the chunk

#pragma unroll
    for (int r = 0; r < 12; r++) {
        int i = r * 256 + tx;
        aR[r] = Fw[(i >> 5) * K3C + (i & 31)];
    }
    bR = catu4[(size_t)(g0 + bcol) * 36 + bq];

    // ---- phase 1: U = Fw @ cat ----
    for (int kb = 0; kb < K3C; kb += KB) {
#pragma unroll
        for (int r = 0; r < 12; r++) {
            int i = r * 256 + tx;
            As[(i & 31) * AP + (i >> 5)] = aR[r];
        }
        {
            int kk = bq * 8;
            Bs[(kk + 0) * BP + bcol] = bf_lo(bR.x);
            Bs[(kk + 1) * BP + bcol] = bf_hi(bR.x);
            Bs[(kk + 2) * BP + bcol] = bf_lo(bR.y);
            Bs[(kk + 3) * BP + bcol] = bf_hi(bR.y);
            Bs[(kk + 4) * BP + bcol] = bf_lo(bR.z);
            Bs[(kk + 5) * BP + bcol] = bf_hi(bR.z);
            Bs[(kk + 6) * BP + bcol] = bf_lo(bR.w);
            Bs[(kk + 7) * BP + bcol] = bf_hi(bR.w);
        }
        __syncthreads();

        int kn = kb + KB;
        if (kn < K3C) {
#pragma unroll
            for (int r = 0; r < 12; r++) {
                int i = r * 256 + tx;
                aR[r] = Fw[(i >> 5) * K3C + kn + (i & 31)];
            }
            bR = catu4[(size_t)(g0 + bcol) * 36 + (kn >> 3) + bq];
        } else {
#pragma unroll
            for (int r = 0; r < 12; r++) {
                int i = r * 256 + tx;
                aR[r] = Pw[(i >> 5) * C_ + (i & 31)];
            }
        }

#pragma unroll
        for (int kk = 0; kk < KB; kk++) {
            ull a01 = *(const ull*)&As[kk * AP + m0];
            ull a23 = *(const ull*)&As[kk * AP + m0 + 2];
            ull a45 = *(const ull*)&As[kk * AP + m0 + 4];
            float4 b = *(const float4*)&Bs[kk * BP + col0];
            ull bx = pack2(b.x, b.x), by = pack2(b.y, b.y);
            ull bz = pack2(b.z, b.z), bw = pack2(b.w, b.w);
            acc[0][0] = ffma2(a01, bx, acc[0][0]);
            acc[0][1] = ffma2(a01, by, acc[0][1]);
            acc[0][2] = ffma2(a01, bz, acc[0][2]);
            acc[0][3] = ffma2(a01, bw, acc[0][3]);
            acc[1][0] = ffma2(a23, bx, acc[1][0]);
            acc[1][1] = ffma2(a23, by, acc[1][1]);
            acc[1][2] = ffma2(a23, bz, acc[1][2]);
            acc[1][3] = ffma2(a23, bw, acc[1][3]);
            acc[2][0] = ffma2(a45, bx, acc[2][0]);
            acc[2][1] = ffma2(a45, by, acc[2][1]);
            acc[2][2] = ffma2(a45, bz, acc[2][2]);
            acc[2][3] = ffma2(a45, bw, acc[2][3]);
        }
        __syncthreads();
    }

    // epilogue 1: +fb, *soft -> Us
    {
        int head = m0 / HD_;
        float4 sf = *(const float4*)&g_soft[head * PTOT + g0 + col0];
#pragma unroll
        for (int jp = 0; jp < 3; jp++) {
            int m = m0 + 2 * jp;
            float f0 = fb[m], f1 = fb[m + 1];
            float4 r0, r1;
            unpack2(acc[jp][0], r0.x, r1.x);
            unpack2(acc[jp][1], r0.y, r1.y);
            unpack2(acc[jp][2], r0.z, r1.z);
            unpack2(acc[jp][3], r0.w, r1.w);
            r0.x = (r0.x + f0) * sf.x; r0.y = (r0.y + f0) * sf.y;
            r0.z = (r0.z + f0) * sf.z; r0.w = (r0.w + f0) * sf.w;
            r1.x = (r1.x + f1) * sf.x; r1.y = (r1.y + f1) * sf.y;
            r1.z = (r1.z + f1) * sf.z; r1.w = (r1.w + f1) * sf.w;
            *(float4*)&Us[m * BP + col0] = r0;
            *(float4*)&Us[(m + 1) * BP + col0] = r1;
        }
    }
    __syncthreads();

    // ---- phase 2: out = Pw @ U ----
    ull acc2[3][4];
#pragma unroll
    for (int jp = 0; jp < 3; jp++)
#pragma unroll
        for (int c = 0; c < 4; c++) acc2[jp][c] = 0ull;

    for (int cb = 0; cb < C_; cb += KB) {
#pragma unroll
        for (int r = 0; r < 12; r++) {
            int i = r * 256 + tx;
            As[(i & 31) * AP + (i >> 5)] = aR[r];
        }
        __syncthreads();

        int cn = cb + KB;
        if (cn < C_) {
#pragma unroll
            for (int r = 0; r < 12; r++) {
                int i = r * 256 + tx;
                aR[r] = Pw[(i >> 5) * C_ + cn + (i & 31)];
            }
        }

#pragma unroll
        for (int kk = 0; kk < KB; kk++) {
            ull a01 = *(const ull*)&As[kk * AP + m0];
            ull a23 = *(const ull*)&As[kk * AP + m0 + 2];
            ull a45 = *(const ull*)&As[kk * AP + m0 + 4];
            float4 b = *(const float4*)&Us[(cb + kk) * BP + col0];
            ull bx = pack2(b.x, b.x), by = pack2(b.y, b.y);
            ull bz = pack2(b.z, b.z), bw = pack2(b.w, b.w);
            acc2[0][0] = ffma2(a01, bx, acc2[0][0]);
            acc2[0][1] = ffma2(a01, by, acc2[0][1]);
            acc2[0][2] = ffma2(a01, bz, acc2[0][2]);
            acc2[0][3] = ffma2(a01, bw, acc2[0][3]);
            acc2[1][0] = ffma2(a23, bx, acc2[1][0]);
            acc2[1][1] = ffma2(a23, by, acc2[1][1]);
            acc2[1][2] = ffma2(a23, bz, acc2[1][2]);
            acc2[1][3] = ffma2(a23, bw, acc2[1][3]);
            acc2[2][0] = ffma2(a45, bx, acc2[2][0]);
            acc2[2][1] = ffma2(a45, by, acc2[2][1]);
            acc2[2][2] = ffma2(a45, bz, acc2[2][2]);
            acc2[2][3] = ffma2(a45, bw, acc2[2][3]);
        }
        __syncthreads();
    }

    // epilogue 2: + pbias + anchor -> out
#pragma unroll
    for (int jp = 0; jp < 3; jp++) {
        int d = m0 + 2 * jp;
        float p0b = pbias[d], p1b = pbias[d + 1];
        float4 a0 = *(const float4*)(anchor + (size_t)(n * C_ + d) * HW_ + p0 + col0);
        float4 a1 = *(const float4*)(anchor + (size_t)(n * C_ + d + 1) * HW_ + p0 + col0);
        float4 r0, r1;
        unpack2(acc2[jp][0], r0.x, r1.x);
        unpack2(acc2[jp][1], r0.y, r1.y);
        unpack2(acc2[jp][2], r0.z, r1.z);
        unpack2(acc2[jp][3], r0.w, r1.w);
        r0.x = r0.x + p0b + a0.x; r0.y = r0.y + p0b + a0.y;
        r0.z = r0.z + p0b + a0.z; r0.w = r0.w + p0b + a0.w;
        r1.x = r1.x + p1b + a1.x; r1.y = r1.y + p1b + a1.y;
        r1.z = r1.z + p1b + a1.z; r1.w = r1.w + p1b + a1.w;
        *(float4*)(out + (size_t)(n * C_ + d) * HW_ + p0 + col0) = r0;
        *(float4*)(out + (size_t)(n * C_ + d + 1) * HW_ + p0 + col0) = r1;
    }
}

// ---------------------------------------------------------------------------
extern "C" void kernel_launch(void* const* d_in, const int* in_sizes, int n_in,
                              void* d_out, int out_size)
{
    const float* curr   = (const float*)d_in[0];
    const float* idxf   = (const float*)d_in[1];
    const float* anchor = (const float*)d_in[2];
    const float* s1     = (const float*)d_in[3];
    const float* s2     = (const float*)d_in[4];
    const float* s3     = (const float*)d_in[5];
    const float* loc    = (const float*)d_in[6];
    const float* pw     = (const float*)d_in[7];
    const float* pbv    = (const float*)d_in[8];
    const float* fw     = (const float*)d_in[9];
    const float* fbv    = (const float*)d_in[10];
    float* out = (float*)d_out;

    k0_transpose<<<dim3(HW_ / 256, C_ / 32, N_ * T_), 256>>>(idxf);
    k1_corr<<<PTOT / 32, 256>>>(curr, s1, s2, s3, loc);
    k23_gemm<<<PTOT / PB, 256>>>(fw, fbv, pw, pbv, anchor, out);
}

// round 15
// speedup vs baseline: 1.0884x; 1.0120x over previous
#include <cuda_runtime.h>
#include <cuda_bf16.h>

// Problem constants
#define N_    2
#define T_    7
#define C_    96
#define HW_   9216
#define W_    96
#define PTOT  18432      // N_*HW_
#define NHEAD 4
#define HD_   24
#define K3C   288        // 3*C_
#define KU    144        // K3C/2 u32 words per pixel row

typedef unsigned int       u32;
typedef unsigned long long ull;

__device__ __forceinline__ ull pack2(float x, float y) {
    ull r; asm("mov.b64 %0, {%1, %2};" : "=l"(r) : "f"(x), "f"(y)); return r;
}
__device__ __forceinline__ void unpack2(ull v, float& x, float& y) {
    asm("mov.b64 {%0, %1}, %2;" : "=f"(x), "=f"(y) : "l"(v));
}
__device__ __forceinline__ ull ffma2(ull a, ull b, ull c) {
    ull d; asm("fma.rn.f32x2 %0, %1, %2, %3;" : "=l"(d) : "l"(a), "l"(b), "l"(c)); return d;
}
__device__ __forceinline__ u32 bf16x2_pack(float lo, float hi) {
    u32 r;
    asm("cvt.rn.bf16x2.f32 %0, %1, %2;" : "=r"(r) : "f"(hi), "f"(lo));  // first src = upper half
    return r;
}
// bf16 -> f32 is a 16-bit left shift of the bit pattern
__device__ __forceinline__ float bf_lo(u32 w) { return __uint_as_float(w << 16); }
__device__ __forceinline__ float bf_hi(u32 w) { return __uint_as_float(w & 0xFFFF0000u); }

// Scratch (static device arrays; no runtime allocation)
__device__ float g_kT[N_ * T_ * HW_ * C_];   // transposed index feats
__device__ u32   g_cat[PTOT * KU];           // [g][144] bf16x2 pairs
__device__ float g_soft[NHEAD * PTOT];       // [head][g]

// ---------------------------------------------------------------------------
// K0: transpose idxf (n,t,c,hw) -> g_kT ((n,t),hw,c).   [unchanged]
// ---------------------------------------------------------------------------
__global__ void __launch_bounds__(256)
k0_transpose(const float* __restrict__ idxf)
{
    __shared__ float tile[4][32][33];
    int nt = blockIdx.z;
    int c0 = blockIdx.y * 32;
    int tid = threadIdx.x;
    int cL = tid >> 3, p4 = (tid & 7) * 4;
    int pL = tid >> 3, c4 = (tid & 7) * 4;

#pragma unroll
    for (int half = 0; half < 2; half++) {
        int pbase = blockIdx.x * 256 + half * 128;
#pragma unroll
        for (int b = 0; b < 4; b++) {
            int p0 = pbase + b * 32;
            float4 v = *(const float4*)(idxf + (size_t)(nt * C_ + c0 + cL) * HW_ + p0 + p4);
            tile[b][cL][p4 + 0] = v.x;
            tile[b][cL][p4 + 1] = v.y;
            tile[b][cL][p4 + 2] = v.z;
            tile[b][cL][p4 + 3] = v.w;
        }
        __syncthreads();
#pragma unroll
        for (int b = 0; b < 4; b++) {
            int p0 = pbase + b * 32;
            float4 o;
            o.x = tile[b][c4 + 0][pL];
            o.y = tile[b][c4 + 1][pL];
            o.z = tile[b][c4 + 2][pL];
            o.w = tile[b][c4 + 3][pL];
            *(float4*)(g_kT + (size_t)(nt * HW_ + p0 + pL) * C_ + c0 + c4) = o;
        }
        __syncthreads();
    }
}

// ---------------------------------------------------------------------------
// K1: correlation + argmax + winner gather; cat stored as bf16x2.  [unchanged]
// ---------------------------------------------------------------------------
__device__ __forceinline__ void red8(float& bs, int& bi)
{
#pragma unroll
    for (int d = 4; d >= 1; d >>= 1) {
        float os = __shfl_xor_sync(0xffffffffu, bs, d, 8);
        int   oi = __shfl_xor_sync(0xffffffffu, bi, d, 8);
        if (os > bs || (os == bs && oi < bi)) { bs = os; bi = oi; }
    }
}

__global__ void __launch_bounds__(256)
k1_corr(const float* __restrict__ curr,
        const float* __restrict__ sp1,
        const float* __restrict__ sp2,
        const float* __restrict__ sp3,
        const float* __restrict__ loc)
{
    __shared__ __align__(16) float sQ[32 * 100];
    __shared__ float sLoc[2 * T_][32];

    int tx = threadIdx.x;
    int lane8 = tx & 7;
    int pb = tx >> 3;
    int g0 = blockIdx.x * 32;
    int g  = g0 + pb;
    int n = g / HW_;
    int p0blk = g0 - n * HW_;
    int t = lane8;

    {
        const float* qsrc = curr + n * C_ * HW_ + p0blk;
        for (int idx = tx; idx < C_ * 32; idx += 256) {
            int c = idx >> 5, pi = idx & 31;
            sQ[pi * 100 + c] = qsrc[c * HW_ + pi];
        }
    }
    {
        const float* lsrc = loc + (size_t)n * 2 * T_ * HW_ + p0blk;
        for (int idx = tx; idx < 2 * T_ * 32; idx += 256) {
            int pl = idx >> 5, pi = idx & 31;
            sLoc[pl][pi] = lsrc[pl * HW_ + pi];
        }
    }
    __syncthreads();

    bool val = false;
    int lin = 0;
    if (t < T_) {
        float lx = sLoc[2 * t][pb];
        float ly = sLoc[2 * t + 1][pb];
        float gx = __fadd_rn(__fdiv_rn(__fmul_rn(2.0f, lx), 95.0f), -1.0f);
        float gy = __fadd_rn(__fdiv_rn(__fmul_rn(2.0f, ly), 95.0f), -1.0f);
        float ixf = rintf(__fmul_rn(__fmul_rn(__fadd_rn(gx, 1.0f), 0.5f), 95.0f));
        float iyf = rintf(__fmul_rn(__fmul_rn(__fadd_rn(gy, 1.0f), 0.5f), 95.0f));
        val = (ixf >= 0.0f) && (ixf <= 95.0f) && (iyf >= 0.0f) && (iyf <= 95.0f);
        int ix = (int)fminf(fmaxf(ixf, 0.0f), 95.0f);
        int iy = (int)fminf(fmaxf(iyf, 0.0f), 95.0f);
        lin = iy * W_ + ix;
    }

    float sA = 0.f, sB = 0.f, sC = 0.f, sD = 0.f;
    float ksq = 0.f, qsq = 0.f;
    bool doK = (t < T_) && val;
    const float4* kp = (const float4*)(g_kT + ((size_t)(n * T_ + t) * HW_ + lin) * C_);
    const float* qrow = sQ + pb * 100;

#pragma unroll
    for (int c4 = 0; c4 < 24; c4++) {
        float4 k4 = doK ? kp[c4] : make_float4(0.f, 0.f, 0.f, 0.f);
        float4 q4 = *(const float4*)(qrow + c4 * 4);
        qsq = fmaf(q4.x, q4.x, fmaf(q4.y, q4.y, fmaf(q4.z, q4.z, fmaf(q4.w, q4.w, qsq))));
        ksq = fmaf(k4.x, k4.x, fmaf(k4.y, k4.y, fmaf(k4.z, k4.z, fmaf(k4.w, k4.w, ksq))));
        float d = fmaf(q4.x, k4.x, fmaf(q4.y, k4.y, fmaf(q4.z, k4.z, q4.w * k4.w)));
        if      (c4 <  6) sA += d;
        else if (c4 < 12) sB += d;
        else if (c4 < 18) sC += d;
        else              sD += d;
    }

    float rk = 1.0f / fmaxf(sqrtf(ksq), 1e-12f);
    float NEGINF = __int_as_float(0xff800000);
    float b0 = (t < T_) ? sA * rk : NEGINF;
    float b1 = (t < T_) ? sB * rk : NEGINF;
    float b2 = (t < T_) ? sC * rk : NEGINF;
    float b3 = (t < T_) ? sD * rk : NEGINF;
    int i0 = t, i1 = t, i2 = t, i3 = t;
    red8(b0, i0);
    red8(b1, i1);
    red8(b2, i2);
    red8(b3, i3);

    float rq = 1.0f / fmaxf(sqrtf(qsq), 1e-12f);
    if (lane8 == 0) g_soft[0 * PTOT + g] = b0 * rq;
    if (lane8 == 1) g_soft[1 * PTOT + g] = b1 * rq;
    if (lane8 == 2) g_soft[2 * PTOT + g] = b2 * rq;
    if (lane8 == 3) g_soft[3 * PTOT + g] = b3 * rq;

    int vflag = val ? 1 : 0;
    int bw[NHEAD], lw[NHEAD], vw[NHEAD];
    bw[0] = i0; bw[1] = i1; bw[2] = i2; bw[3] = i3;
#pragma unroll
    for (int h = 0; h < NHEAD; h++) {
        lw[h] = __shfl_sync(0xffffffffu, lin,   bw[h], 8);
        vw[h] = __shfl_sync(0xffffffffu, vflag, bw[h], 8);
    }

    u32* catg = g_cat + (size_t)g * KU;
#pragma unroll
    for (int h = 0; h < NHEAD; h++) {
        int bofs = ((n * T_ + bw[h]) * C_ + h * HD_) * HW_ + lw[h];
        bool v = (vw[h] != 0);
#pragma unroll
        for (int j = 0; j < 5; j++) {
            int pi = lane8 + j * 8;
            if (j < 4 || pi < 36) {
                int ch0 = 2 * pi;
                int set = ch0 / 24;
                int cc  = ch0 - set * 24;
                const float* sp = (set == 0) ? sp1 : ((set == 1) ? sp2 : sp3);
                float v0 = v ? __ldg(sp + bofs + cc * HW_)       : 0.0f;
                float v1 = v ? __ldg(sp + bofs + (cc + 1) * HW_) : 0.0f;
                catg[set * 48 + h * 12 + (cc >> 1)] = bf16x2_pack(v0, v1);
            }
        }
    }
}

// ---------------------------------------------------------------------------
// K23 fused: KB=32, 256 threads, 6x4 FFMA2 microtile.
//   AP=102: bank stride 6 -> 2-way STS conflict (104 was 8-way), rows 8B-aligned.
//   minocc 3: smem 47KB x3 = 141KB, hides LDS/barrier latency.
// ---------------------------------------------------------------------------
#define PB 64
#define KB 32
#define AP 102
#define BP 68

__global__ void __launch_bounds__(256, 3)
k23_gemm(const float* __restrict__ Fw, const float* __restrict__ fb,
         const float* __restrict__ Pw, const float* __restrict__ pbias,
         const float* __restrict__ anchor, float* __restrict__ out)
{
    __shared__ __align__(16) float As[KB * AP];
    __shared__ __align__(16) float Bs[KB * BP];
    __shared__ __align__(16) float Us[C_ * BP];

    int g0 = blockIdx.x * PB;
    int n  = g0 / HW_;
    int p0 = g0 - n * HW_;
    int tx = threadIdx.x;
    int m0   = (tx >> 4) * 6;
    int col0 = (tx & 15) * 4;

    ull acc[3][4];
#pragma unroll
    for (int jp = 0; jp < 3; jp++)
#pragma unroll
        for (int c = 0; c < 4; c++) acc[jp][c] = 0ull;

    const uint4* catu4 = (const uint4*)g_cat;

    float aR[12];
    uint4 bR;

    int bcol = tx >> 2;
    int bq   = tx & 3;

#pragma unroll
    for (int r = 0; r < 12; r++) {
        int i = r * 256 + tx;
        aR[r] = Fw[(i >> 5) * K3C + (i & 31)];
    }
    bR = catu4[(size_t)(g0 + bcol) * 36 + bq];

    // ---- phase 1: U = Fw @ cat ----
    for (int kb = 0; kb < K3C; kb += KB) {
#pragma unroll
        for (int r = 0; r < 12; r++) {
            int i = r * 256 + tx;
            As[(i & 31) * AP + (i >> 5)] = aR[r];
        }
        {
            int kk = bq * 8;
            Bs[(kk + 0) * BP + bcol] = bf_lo(bR.x);
            Bs[(kk + 1) * BP + bcol] = bf_hi(bR.x);
            Bs[(kk + 2) * BP + bcol] = bf_lo(bR.y);
            Bs[(kk + 3) * BP + bcol] = bf_hi(bR.y);
            Bs[(kk + 4) * BP + bcol] = bf_lo(bR.z);
            Bs[(kk + 5) * BP + bcol] = bf_hi(bR.z);
            Bs[(kk + 6) * BP + bcol] = bf_lo(bR.w);
            Bs[(kk + 7) * BP + bcol] = bf_hi(bR.w);
        }
        __syncthreads();

        int kn = kb + KB;
        if (kn < K3C) {
#pragma unroll
            for (int r = 0; r < 12; r++) {
                int i = r * 256 + tx;
                aR[r] = Fw[(i >> 5) * K3C + kn + (i & 31)];
            }
            bR = catu4[(size_t)(g0 + bcol) * 36 + (kn >> 3) + bq];
        } else {
#pragma unroll
            for (int r = 0; r < 12; r++) {
                int i = r * 256 + tx;
                aR[r] = Pw[(i >> 5) * C_ + (i & 31)];
            }
        }

#pragma unroll
        for (int kk = 0; kk < KB; kk++) {
            ull a01 = *(const ull*)&As[kk * AP + m0];
            ull a23 = *(const ull*)&As[kk * AP + m0 + 2];
            ull a45 = *(const ull*)&As[kk * AP + m0 + 4];
            float4 b = *(const float4*)&Bs[kk * BP + col0];
            ull bx = pack2(b.x, b.x), by = pack2(b.y, b.y);
            ull bz = pack2(b.z, b.z), bw = pack2(b.w, b.w);
            acc[0][0] = ffma2(a01, bx, acc[0][0]);
            acc[0][1] = ffma2(a01, by, acc[0][1]);
            acc[0][2] = ffma2(a01, bz, acc[0][2]);
            acc[0][3] = ffma2(a01, bw, acc[0][3]);
            acc[1][0] = ffma2(a23, bx, acc[1][0]);
            acc[1][1] = ffma2(a23, by, acc[1][1]);
            acc[1][2] = ffma2(a23, bz, acc[1][2]);
            acc[1][3] = ffma2(a23, bw, acc[1][3]);
            acc[2][0] = ffma2(a45, bx, acc[2][0]);
            acc[2][1] = ffma2(a45, by, acc[2][1]);
            acc[2][2] = ffma2(a45, bz, acc[2][2]);
            acc[2][3] = ffma2(a45, bw, acc[2][3]);
        }
        __syncthreads();
    }

    // epilogue 1: +fb, *soft -> Us
    {
        int head = m0 / HD_;
        float4 sf = *(const float4*)&g_soft[head * PTOT + g0 + col0];
#pragma unroll
        for (int jp = 0; jp < 3; jp++) {
            int m = m0 + 2 * jp;
            float f0 = fb[m], f1 = fb[m + 1];
            float4 r0, r1;
            unpack2(acc[jp][0], r0.x, r1.x);
            unpack2(acc[jp][1], r0.y, r1.y);
            unpack2(acc[jp][2], r0.z, r1.z);
            unpack2(acc[jp][3], r0.w, r1.w);
            r0.x = (r0.x + f0) * sf.x; r0.y = (r0.y + f0) * sf.y;
            r0.z = (r0.z + f0) * sf.z; r0.w = (r0.w + f0) * sf.w;
            r1.x = (r1.x + f1) * sf.x; r1.y = (r1.y + f1) * sf.y;
            r1.z = (r1.z + f1) * sf.z; r1.w = (r1.w + f1) * sf.w;
            *(float4*)&Us[m * BP + col0] = r0;
            *(float4*)&Us[(m + 1) * BP + col0] = r1;
        }
    }
    __syncthreads();

    // ---- phase 2: out = Pw @ U ----
    ull acc2[3][4];
#pragma unroll
    for (int jp = 0; jp < 3; jp++)
#pragma unroll
        for (int c = 0; c < 4; c++) acc2[jp][c] = 0ull;

    for (int cb = 0; cb < C_; cb += KB) {
#pragma unroll
        for (int r = 0; r < 12; r++) {
            int i = r * 256 + tx;
            As[(i & 31) * AP + (i >> 5)] = aR[r];
        }
        __syncthreads();

        int cn = cb + KB;
        if (cn < C_) {
#pragma unroll
            for (int r = 0; r < 12; r++) {
                int i = r * 256 + tx;
                aR[r] = Pw[(i >> 5) * C_ + cn + (i & 31)];
            }
        }

#pragma unroll
        for (int kk = 0; kk < KB; kk++) {
            ull a01 = *(const ull*)&As[kk * AP + m0];
            ull a23 = *(const ull*)&As[kk * AP + m0 + 2];
            ull a45 = *(const ull*)&As[kk * AP + m0 + 4];
            float4 b = *(const float4*)&Us[(cb + kk) * BP + col0];
            ull bx = pack2(b.x, b.x), by = pack2(b.y, b.y);
            ull bz = pack2(b.z, b.z), bw = pack2(b.w, b.w);
            acc2[0][0] = ffma2(a01, bx, acc2[0][0]);
            acc2[0][1] = ffma2(a01, by, acc2[0][1]);
            acc2[0][2] = ffma2(a01, bz, acc2[0][2]);
            acc2[0][3] = ffma2(a01, bw, acc2[0][3]);
            acc2[1][0] = ffma2(a23, bx, acc2[1][0]);
            acc2[1][1] = ffma2(a23, by, acc2[1][1]);
            acc2[1][2] = ffma2(a23, bz, acc2[1][2]);
            acc2[1][3] = ffma2(a23, bw, acc2[1][3]);
            acc2[2][0] = ffma2(a45, bx, acc2[2][0]);
            acc2[2][1] = ffma2(a45, by, acc2[2][1]);
            acc2[2][2] = ffma2(a45, bz, acc2[2][2]);
            acc2[2][3] = ffma2(a45, bw, acc2[2][3]);
        }
        __syncthreads();
    }

    // epilogue 2: + pbias + anchor -> out
#pragma unroll
    for (int jp = 0; jp < 3; jp++) {
        int d = m0 + 2 * jp;
        float p0b = pbias[d], p1b = pbias[d + 1];
        float4 a0 = *(const float4*)(anchor + (size_t)(n * C_ + d) * HW_ + p0 + col0);
        float4 a1 = *(const float4*)(anchor + (size_t)(n * C_ + d + 1) * HW_ + p0 + col0);
        float4 r0, r1;
        unpack2(acc2[jp][0], r0.x, r1.x);
        unpack2(acc2[jp][1], r0.y, r1.y);
        unpack2(acc2[jp][2], r0.z, r1.z);
        unpack2(acc2[jp][3], r0.w, r1.w);
        r0.x = r0.x + p0b + a0.x; r0.y = r0.y + p0b + a0.y;
        r0.z = r0.z + p0b + a0.z; r0.w = r0.w + p0b + a0.w;
        r1.x = r1.x + p1b + a1.x; r1.y = r1.y + p1b + a1.y;
        r1.z = r1.z + p1b + a1.z; r1.w = r1.w + p1b + a1.w;
        *(float4*)(out + (size_t)(n * C_ + d) * HW_ + p0 + col0) = r0;
        *(float4*)(out + (size_t)(n * C_ + d + 1) * HW_ + p0 + col0) = r1;
    }
}

// ---------------------------------------------------------------------------
extern "C" void kernel_launch(void* const* d_in, const int* in_sizes, int n_in,
                              void* d_out, int out_size)
{
    const float* curr   = (const float*)d_in[0];
    const float* idxf   = (const float*)d_in[1];
    const float* anchor = (const float*)d_in[2];
    const float* s1     = (const float*)d_in[3];
    const float* s2     = (const float*)d_in[4];
    const float* s3     = (const float*)d_in[5];
    const float* loc    = (const float*)d_in[6];
    const float* pw     = (const float*)d_in[7];
    const float* pbv    = (const float*)d_in[8];
    const float* fw     = (const float*)d_in[9];
    const float* fbv    = (const float*)d_in[10];
    float* out = (float*)d_out;

    k0_transpose<<<dim3(HW_ / 256, C_ / 32, N_ * T_), 256>>>(idxf);
    k1_corr<<<PTOT / 32, 256>>>(curr, s1, s2, s3, loc);
    k23_gemm<<<PTOT / PB, 256>>>(fw, fbv, pw, pbv, anchor, out);
}